// round 9
// baseline (speedup 1.0000x reference)
#include <cuda_runtime.h>
#include <cuda_fp16.h>
#include <cstdint>

#define Bv 16
#define Cv 64
#define Hv 128
#define Wv 128
#define HCv 64

// Pre-baked W image (fp16): [chunk(3)][m(256)][k(64) octet-swizzled] = 96 KB
__device__ __align__(16) uint16_t g_wimg[3 * 256 * 64];
// Pre-rounded X plane (fp16), layout [b][ic][h][w]
#define XN ((size_t)Bv * Cv * Hv * Wv)
__device__ __align__(16) __half g_xhi[XN];

// ---- smem map (bytes) ----
// W resident 0..98304 ; XBUF 2 x 16KB at 98304..131072
// GATES fp16 at 131072: addr = GATE_B + w*512 + ((2m) ^ ((w&7)<<4))  (64KB)
// PS (scan partials) at 196608: float2 (P,c) per (seg(16), hc(64)) = 8KB
#define XBUF_B 98304
#define GATE_B 131072
#define PS_B   196608
#define SMEM_BYTES 204800

extern __shared__ uint32_t smw[];

__device__ __forceinline__ uint32_t smem_u32(const void* p) {
    uint32_t a;
    asm("{ .reg .u64 t; cvta.to.shared.u64 t, %1; cvt.u32.u64 %0, t; }"
        : "=r"(a) : "l"(p));
    return a;
}

__device__ __forceinline__ float rcp_fast(float d) {
    float r;
    asm("rcp.approx.ftz.f32 %0, %1;" : "=f"(r) : "f"(d));
    return r;
}

// quad sigmoid: one RCP for four values
__device__ __forceinline__ void sigmoid4(float* v) {
    float e0 = __expf(-v[0]), e1 = __expf(-v[1]);
    float e2 = __expf(-v[2]), e3 = __expf(-v[3]);
    float p0 = 1.f + e0, p1 = 1.f + e1, p2 = 1.f + e2, p3 = 1.f + e3;
    float q01 = p0 * p1, q23 = p2 * p3;
    float rr = rcp_fast(q01 * q23);
    float r01 = q23 * rr, r23 = q01 * rr;
    v[0] = p1 * r01; v[1] = p0 * r01;
    v[2] = p3 * r23; v[3] = p2 * r23;
}
// quad tanh: one RCP for four values
__device__ __forceinline__ void tanh4(float* v) {
    float e0 = __expf(-2.f * fabsf(v[0])), e1 = __expf(-2.f * fabsf(v[1]));
    float e2 = __expf(-2.f * fabsf(v[2])), e3 = __expf(-2.f * fabsf(v[3]));
    float p0 = 1.f + e0, p1 = 1.f + e1, p2 = 1.f + e2, p3 = 1.f + e3;
    float q01 = p0 * p1, q23 = p2 * p3;
    float rr = rcp_fast(q01 * q23);
    float r01 = q23 * rr, r23 = q01 * rr;
    float t0 = (1.f - e0) * p1 * r01, t1 = (1.f - e1) * p0 * r01;
    float t2 = (1.f - e2) * p3 * r23, t3 = (1.f - e3) * p2 * r23;
    v[0] = (v[0] < 0.f) ? -t0 : t0;
    v[1] = (v[1] < 0.f) ? -t1 : t1;
    v[2] = (v[2] < 0.f) ? -t2 : t2;
    v[3] = (v[3] < 0.f) ? -t3 : t3;
}

__device__ __forceinline__ void mma_f16(float* c, const uint32_t* a,
                                        uint32_t b0, uint32_t b1) {
    asm volatile(
        "mma.sync.aligned.m16n8k16.row.col.f32.f16.f16.f32 "
        "{%0,%1,%2,%3}, {%4,%5,%6,%7}, {%8,%9}, {%0,%1,%2,%3};\n"
        : "+f"(c[0]), "+f"(c[1]), "+f"(c[2]), "+f"(c[3])
        : "r"(a[0]), "r"(a[1]), "r"(a[2]), "r"(a[3]), "r"(b0), "r"(b1));
}

#define LDM4(R, addr) \
    asm volatile("ldmatrix.sync.aligned.m8n8.x4.shared.b16 {%0,%1,%2,%3}, [%4];" \
        : "=r"((R)[0]), "=r"((R)[1]), "=r"((R)[2]), "=r"((R)[3]) : "r"(addr))
#define LDM4T(R, addr) \
    asm volatile("ldmatrix.sync.aligned.m8n8.x4.trans.shared.b16 {%0,%1,%2,%3}, [%4];" \
        : "=r"((R)[0]), "=r"((R)[1]), "=r"((R)[2]), "=r"((R)[3]) : "r"(addr))
#define CPA16(dst, src) \
    asm volatile("cp.async.ca.shared.global [%0], [%1], 16;" :: "r"(dst), "l"(src))
#define CPA16Z(dst, src, sz) \
    asm volatile("cp.async.ca.shared.global [%0], [%1], 16, %2;" \
                 :: "r"(dst), "l"(src), "r"(sz))
#define CPA_COMMIT() asm volatile("cp.async.commit_group;" ::: "memory")
#define CPA_WAIT0()  asm volatile("cp.async.wait_group 0;" ::: "memory")

__device__ __forceinline__ void sts16(uint32_t a, float v) {
    unsigned short u = __half_as_ushort(__float2half_rn(v));
    asm volatile("st.shared.u16 [%0], %1;" :: "r"(a), "h"(u) : "memory");
}

// ---------------------------------------------------------------- prep kernel
__global__ void __launch_bounds__(256)
prep_xw(const float* __restrict__ x, const float* __restrict__ wgt) {
    if (blockIdx.x < 192) {
        int k = blockIdx.x;
        int m = threadIdx.x;
        float v = wgt[m * 192 + k];
        int c = k >> 6, kl = k & 63, o = kl >> 3, e = kl & 7;
        g_wimg[c * 16384 + m * 64 + (((o ^ (m & 7)) << 3) + e)] =
            __half_as_ushort(__float2half_rn(v));
    }
    size_t i = ((size_t)blockIdx.x * 256 + threadIdx.x) * 8;
    float4 a = *reinterpret_cast<const float4*>(x + i);
    float4 c = *reinterpret_cast<const float4*>(x + i + 4);
    float vf[8] = {a.x, a.y, a.z, a.w, c.x, c.y, c.z, c.w};
    uint32_t hw[4];
#pragma unroll
    for (int j = 0; j < 4; j++) {
        __half2 hh = __float22half2_rn(make_float2(vf[2 * j], vf[2 * j + 1]));
        hw[j] = *reinterpret_cast<uint32_t*>(&hh);
    }
    *reinterpret_cast<uint4*>(g_xhi + i) = make_uint4(hw[0], hw[1], hw[2], hw[3]);
}

// ---------------------------------------------------------------- fused kernel
// One block per 2 rows (b, 2p / 2p+1), 512 threads = 16 warps (4m x 4n).
// W (96KB) smem-resident once; X streamed per 64-k chunk via cp.async.
// Gates fp16 in their own region (no aliasing); half2 segmented LSTM scan.
__global__ void __launch_bounds__(512, 1)
rowlstm_fused(const float* __restrict__ bias, float* __restrict__ out) {
    const int tid = threadIdx.x;
    const int lane = tid & 31;
    const int wid = tid >> 5;
    const int mw = wid & 3;
    const int nw = wid >> 2;
    const int r = lane >> 2, cl = lane & 3;
    const int b = blockIdx.x >> 6;
    const int hbase = (blockIdx.x & 63) * 2;

    const uint32_t smb = smem_u32(smw);

    // ldmatrix lane params
    const int l7 = lane & 7, l15 = lane & 15, lk = lane >> 4;
    const int krl = l7 + ((lane & 16) >> 1);
    const int wo = (lane >> 3) & 1;

    uint64_t gw, gxh;
    asm("cvta.to.global.u64 %0, %1;" : "=l"(gw) : "l"((const void*)g_wimg));
    asm("cvta.to.global.u64 %0, %1;" : "=l"(gxh) : "l"((const void*)g_xhi));

// stage X chunk cn for row at height hh into buffer db
#define STAGE_X(hh, cn, db)                                                 \
    do {                                                                    \
        _Pragma("unroll") for (int t = 0; t < 2; t++) {                     \
            int g = t * 512 + tid;                                          \
            int krow = g >> 4;                                              \
            int woct = g & 15;                                              \
            int kg = (cn) * 64 + krow;                                      \
            int ic = kg / 3;                                                \
            int kh = kg - 3 * ic;                                           \
            int hp = (hh) + kh - 2;                                         \
            int sz = (hp >= 0) ? 16 : 0;                                    \
            int hpc = (hp >= 0) ? hp : 0;                                   \
            size_t eoff = (((size_t)(b * Cv + ic) * Hv + hpc) * Wv +        \
                           woct * 8) * 2;                                   \
            uint32_t dst = smb + XBUF_B + (db) * 16384 + krow * 256 +       \
                           ((woct ^ (krow & 7)) << 4);                      \
            CPA16Z(dst, gxh + eoff, sz);                                    \
        }                                                                   \
    } while (0)

    // ---- preamble: W (96KB, once) + X(row0, chunk0) -> buf0
    {
#pragma unroll
        for (int j = 0; j < 12; j++)
            CPA16(smb + tid * 16 + j * 8192, gw + tid * 16 + j * 8192);
        STAGE_X(hbase, 0, 0);
        CPA_COMMIT();
        CPA_WAIT0();
        __syncthreads();
    }

#pragma unroll 1
    for (int row = 0; row < 2; row++) {
        const int hrow = hbase + row;

        float acc[4][4][4];
#pragma unroll
        for (int mt = 0; mt < 4; mt++)
#pragma unroll
            for (int nt = 0; nt < 4; nt++)
#pragma unroll
                for (int q = 0; q < 4; q++) acc[mt][nt][q] = 0.0f;

#pragma unroll
        for (int c = 0; c < 3; c++) {
            const int db = (3 * row + c) & 1;
            if (c < 2) {
                STAGE_X(hrow, c + 1, db ^ 1);
                CPA_COMMIT();
            } else if (row == 0) {
                STAGE_X(hbase + 1, 0, db ^ 1);  // prefetch row1 chunk0 under tail
                CPA_COMMIT();
            }

            const uint32_t a_h = smb + c * 32768 + (mw * 64 + l15) * 128;
            uint32_t bb[2];
#pragma unroll
            for (int np = 0; np < 2; np++) {
                int oct = ((nw * 32 + np * 16) >> 3) + wo;
                bb[np] = smb + XBUF_B + db * 16384 + krl * 256 + ((oct ^ l7) << 4);
            }
#pragma unroll
            for (int ks = 0; ks < 4; ks++) {
                uint32_t Bh[2][4];
#pragma unroll
                for (int np = 0; np < 2; np++)
                    LDM4T(Bh[np], bb[np] + ks * 4096);
                const uint32_t swA = (uint32_t)(((2 * ks + lk) ^ l7) << 4);
#pragma unroll
                for (int mt = 0; mt < 4; mt++) {
                    uint32_t A[4];
                    LDM4(A, a_h + mt * 2048 + swA);
#pragma unroll
                    for (int nt = 0; nt < 4; nt++) {
                        const int np = nt >> 1, ix = nt & 1;
                        mma_f16(acc[mt][nt], A, Bh[np][ix], Bh[np][2 + ix]);
                    }
                }
            }

            if (c < 2) {
                CPA_WAIT0();
                __syncthreads();
            }
        }

        // ---- epilogue: bias + activation -> gates fp16 (swizzled)
        const bool isg = (mw == 3);
#pragma unroll
        for (int mt = 0; mt < 4; mt++) {
            const int m0 = mw * 64 + mt * 16;
            const float blo = bias[m0 + r];
            const float bhi = bias[m0 + 8 + r];
            const uint32_t mlo2 = 2u * (uint32_t)(m0 + r);
            const uint32_t mhi2 = mlo2 + 16u;
#pragma unroll
            for (int nt = 0; nt < 4; nt++) {
                const int w0 = nw * 32 + nt * 8 + 2 * cl;
                float v[4];
                v[0] = acc[mt][nt][0] + blo;
                v[1] = acc[mt][nt][1] + blo;
                v[2] = acc[mt][nt][2] + bhi;
                v[3] = acc[mt][nt][3] + bhi;
                if (isg) tanh4(v); else sigmoid4(v);
                const uint32_t sw0 = (uint32_t)((w0 & 7) << 4);
                const uint32_t sw1 = sw0 + 16u;
                const uint32_t base = smb + GATE_B + (uint32_t)w0 * 512;
                sts16(base + (mlo2 ^ sw0), v[0]);
                sts16(base + 512 + (mlo2 ^ sw1), v[1]);
                sts16(base + (mhi2 ^ sw0), v[2]);
                sts16(base + 512 + (mhi2 ^ sw1), v[3]);
            }
        }
        __syncthreads();

        // ---- LSTM scan: 16 segments x 8 w; each thread: 2 hc (half2 loads)
        {
            const int sseg = tid >> 5;
            const int wb2 = sseg * 8;
            const uint32_t gscan = smb + GATE_B + (uint32_t)wb2 * 512;
            const uint32_t mo = 4u * (uint32_t)lane;   // 2m bytes for hc=2*lane

            float cA[16], PA[16];
            float c0 = 0.f, c1 = 0.f, p0 = 1.f, p1 = 1.f;
#pragma unroll
            for (int j = 0; j < 8; j++) {
                const uint32_t ofs = (mo ^ (uint32_t)(j << 4)) + (uint32_t)j * 512;
                uint32_t iw, fw, gw2;
                asm volatile("ld.shared.u32 %0, [%1];" : "=r"(iw) : "r"(gscan + ofs));
                asm volatile("ld.shared.u32 %0, [%1];" : "=r"(fw) : "r"(gscan + ofs + 128));
                asm volatile("ld.shared.u32 %0, [%1];" : "=r"(gw2) : "r"(gscan + ofs + 384));
                float2 iv = __half22float2(*reinterpret_cast<__half2*>(&iw));
                float2 fv = __half22float2(*reinterpret_cast<__half2*>(&fw));
                float2 gv = __half22float2(*reinterpret_cast<__half2*>(&gw2));
                c0 = fmaf(fv.x, c0, iv.x * gv.x); p0 *= fv.x;
                c1 = fmaf(fv.y, c1, iv.y * gv.y); p1 *= fv.y;
                cA[2 * j] = c0; cA[2 * j + 1] = c1;
                PA[2 * j] = p0; PA[2 * j + 1] = p1;
            }
            {
                uint32_t psa = smb + PS_B + (uint32_t)(sseg * 64 + 2 * lane) * 8;
                asm volatile("st.shared.v4.b32 [%0], {%1,%2,%3,%4};"
                             :: "r"(psa), "f"(p0), "f"(c0), "f"(p1), "f"(c1)
                             : "memory");
            }
            __syncthreads();

            float cin0 = 0.f, cin1 = 0.f;
#pragma unroll
            for (int s2 = 0; s2 < 15; s2++) {
                if (s2 < sseg) {
                    uint32_t psa = smb + PS_B + (uint32_t)(s2 * 64 + 2 * lane) * 8;
                    float q0, q1, q2, q3;
                    asm volatile("ld.shared.v4.b32 {%0,%1,%2,%3}, [%4];"
                                 : "=f"(q0), "=f"(q1), "=f"(q2), "=f"(q3)
                                 : "r"(psa));
                    cin0 = fmaf(q0, cin0, q1);
                    cin1 = fmaf(q2, cin1, q3);
                }
            }

            float h0v[8], h1v[8];
#pragma unroll
            for (int j = 0; j < 8; j += 2) {
                const uint32_t oA = (mo ^ (uint32_t)(j << 4)) + (uint32_t)j * 512 + 256;
                const uint32_t oB = (mo ^ (uint32_t)((j + 1) << 4)) +
                                    (uint32_t)(j + 1) * 512 + 256;
                uint32_t owA, owB;
                asm volatile("ld.shared.u32 %0, [%1];" : "=r"(owA) : "r"(gscan + oA));
                asm volatile("ld.shared.u32 %0, [%1];" : "=r"(owB) : "r"(gscan + oB));
                float2 ovA = __half22float2(*reinterpret_cast<__half2*>(&owA));
                float2 ovB = __half22float2(*reinterpret_cast<__half2*>(&owB));
                float t[4];
                t[0] = fmaf(PA[2 * j],     cin0, cA[2 * j]);
                t[1] = fmaf(PA[2 * j + 1], cin1, cA[2 * j + 1]);
                t[2] = fmaf(PA[2 * j + 2], cin0, cA[2 * j + 2]);
                t[3] = fmaf(PA[2 * j + 3], cin1, cA[2 * j + 3]);
                tanh4(t);
                h0v[j]     = ovA.x * t[0];
                h1v[j]     = ovA.y * t[1];
                h0v[j + 1] = ovB.x * t[2];
                h1v[j + 1] = ovB.y * t[3];
            }
            float* o0 = out + ((size_t)(b * HCv + 2 * lane) * Hv + hrow) * Wv + wb2;
            float* o1 = o0 + (size_t)Hv * Wv;
            *reinterpret_cast<float4*>(o0) =
                make_float4(h0v[0], h0v[1], h0v[2], h0v[3]);
            *reinterpret_cast<float4*>(o0 + 4) =
                make_float4(h0v[4], h0v[5], h0v[6], h0v[7]);
            *reinterpret_cast<float4*>(o1) =
                make_float4(h1v[0], h1v[1], h1v[2], h1v[3]);
            *reinterpret_cast<float4*>(o1 + 4) =
                make_float4(h1v[4], h1v[5], h1v[6], h1v[7]);
        }
        __syncthreads();

        if (row == 0) {          // row1 chunk0 cp.async (issued pre-tail) done?
            CPA_WAIT0();
            __syncthreads();
        }
    }
}

extern "C" void kernel_launch(void* const* d_in, const int* in_sizes, int n_in,
                              void* d_out, int out_size) {
    const float* x    = (const float*)d_in[0];
    const float* wgt  = (const float*)d_in[1];
    const float* bias = (const float*)d_in[2];
    float* out = (float*)d_out;

    cudaFuncSetAttribute(rowlstm_fused,
                         cudaFuncAttributeMaxDynamicSharedMemorySize, SMEM_BYTES);

    prep_xw<<<8192, 256>>>(x, wgt);
    rowlstm_fused<<<1024, 512, SMEM_BYTES>>>(bias, out);
}

// round 10
// speedup vs baseline: 1.1684x; 1.1684x over previous
#include <cuda_runtime.h>
#include <cuda_fp16.h>
#include <cstdint>

#define Bv 16
#define Cv 64
#define Hv 128
#define Wv 128
#define HCv 64

// Pre-baked W image (fp16): [chunk(3)][m(256)][k(64) octet-swizzled] = 96 KB
__device__ __align__(16) uint16_t g_wimg[3 * 256 * 64];
// Pre-rounded X plane (fp16), layout [b][ic][h][w]
#define XN ((size_t)Bv * Cv * Hv * Wv)
__device__ __align__(16) __half g_xhi[XN];

// ---- smem map (bytes) ----
// W resident: 3 x 32KB at 0 ; XBUF: 2 x 16KB at 98304 -> 131072
// after mainloop (aliased): gates fp32 [w(128)][260 words] + PS at word 33280
#define XBUF_B   98304
#define GST      260
#define PS_W     33280
#define SMEM_BYTES 137216

extern __shared__ uint32_t smw[];

__device__ __forceinline__ uint32_t smem_u32(const void* p) {
    uint32_t a;
    asm("{ .reg .u64 t; cvta.to.shared.u64 t, %1; cvt.u32.u64 %0, t; }"
        : "=r"(a) : "l"(p));
    return a;
}

// single-instruction MUFU.TANH
__device__ __forceinline__ float tanh_f(float x) {
    float y;
    asm("tanh.approx.f32 %0, %1;" : "=f"(y) : "f"(x));
    return y;
}
// sigmoid via tanh: 1 MUFU + 1 FMA + 1 MUL
__device__ __forceinline__ float sigmoid_f(float x) {
    return fmaf(tanh_f(0.5f * x), 0.5f, 0.5f);
}

__device__ __forceinline__ void mma_f16(float* c, const uint32_t* a,
                                        uint32_t b0, uint32_t b1) {
    asm volatile(
        "mma.sync.aligned.m16n8k16.row.col.f32.f16.f16.f32 "
        "{%0,%1,%2,%3}, {%4,%5,%6,%7}, {%8,%9}, {%0,%1,%2,%3};\n"
        : "+f"(c[0]), "+f"(c[1]), "+f"(c[2]), "+f"(c[3])
        : "r"(a[0]), "r"(a[1]), "r"(a[2]), "r"(a[3]), "r"(b0), "r"(b1));
}

#define LDM4(R, addr) \
    asm volatile("ldmatrix.sync.aligned.m8n8.x4.shared.b16 {%0,%1,%2,%3}, [%4];" \
        : "=r"((R)[0]), "=r"((R)[1]), "=r"((R)[2]), "=r"((R)[3]) : "r"(addr))
#define LDM4T(R, addr) \
    asm volatile("ldmatrix.sync.aligned.m8n8.x4.trans.shared.b16 {%0,%1,%2,%3}, [%4];" \
        : "=r"((R)[0]), "=r"((R)[1]), "=r"((R)[2]), "=r"((R)[3]) : "r"(addr))
#define CPA16(dst, src) \
    asm volatile("cp.async.ca.shared.global [%0], [%1], 16;" :: "r"(dst), "l"(src))
#define CPA16Z(dst, src, sz) \
    asm volatile("cp.async.ca.shared.global [%0], [%1], 16, %2;" \
                 :: "r"(dst), "l"(src), "r"(sz))
#define CPA_COMMIT() asm volatile("cp.async.commit_group;" ::: "memory")
#define CPA_WAIT0()  asm volatile("cp.async.wait_group 0;" ::: "memory")

// ---------------------------------------------------------------- prep kernel
// All blocks: round 8 floats of x to fp16 plane. Blocks 0..191 additionally
// bake one k-column of the W image (k = blockIdx.x, m = threadIdx.x).
__global__ void __launch_bounds__(256)
prep_xw(const float* __restrict__ x, const float* __restrict__ wgt) {
    if (blockIdx.x < 192) {
        int k = blockIdx.x;
        int m = threadIdx.x;
        float v = wgt[m * 192 + k];
        int c = k >> 6, kl = k & 63, o = kl >> 3, e = kl & 7;
        g_wimg[c * 16384 + m * 64 + (((o ^ (m & 7)) << 3) + e)] =
            __half_as_ushort(__float2half_rn(v));
    }
    size_t i = ((size_t)blockIdx.x * 256 + threadIdx.x) * 8;
    float4 a = *reinterpret_cast<const float4*>(x + i);
    float4 c = *reinterpret_cast<const float4*>(x + i + 4);
    float vf[8] = {a.x, a.y, a.z, a.w, c.x, c.y, c.z, c.w};
    uint32_t hw[4];
#pragma unroll
    for (int j = 0; j < 4; j++) {
        __half2 hh = __float22half2_rn(make_float2(vf[2 * j], vf[2 * j + 1]));
        hw[j] = *reinterpret_cast<uint32_t*>(&hh);
    }
    *reinterpret_cast<uint4*>(g_xhi + i) = make_uint4(hw[0], hw[1], hw[2], hw[3]);
}

// ---------------------------------------------------------------- fused kernel
// One block per (b,h), 512 threads = 16 warps (4m x 4n), warp tile 64x32.
// W (96KB) smem-resident; X (fp16 plane) streamed per 64-k chunk via cp.async.
__global__ void __launch_bounds__(512, 1)
rowlstm_fused(const float* __restrict__ bias, float* __restrict__ out) {
    float* smf = reinterpret_cast<float*>(smw);
    const int tid = threadIdx.x;
    const int lane = tid & 31;
    const int wid = tid >> 5;
    const int mw = wid & 3;
    const int nw = wid >> 2;
    const int r = lane >> 2, cl = lane & 3;
    const int bh = blockIdx.x, b = bh >> 7, h = bh & 127;

    const uint32_t smb = smem_u32(smw);

    // ldmatrix lane params
    const int l7 = lane & 7, l15 = lane & 15, lk = lane >> 4;
    const int krl = l7 + ((lane & 16) >> 1);
    const int wo = (lane >> 3) & 1;

    uint64_t gw, gxh;
    asm("cvta.to.global.u64 %0, %1;" : "=l"(gw) : "l"((const void*)g_wimg));
    asm("cvta.to.global.u64 %0, %1;" : "=l"(gxh) : "l"((const void*)g_xhi));

    float acc[4][4][4];
#pragma unroll
    for (int mt = 0; mt < 4; mt++)
#pragma unroll
        for (int nt = 0; nt < 4; nt++)
#pragma unroll
            for (int q = 0; q < 4; q++) acc[mt][nt][q] = 0.0f;

// stage X chunk cn into buffer db: per thread 2 granules (1024 total = 16KB)
#define STAGE_X(cn, db)                                                     \
    do {                                                                    \
        _Pragma("unroll") for (int t = 0; t < 2; t++) {                     \
            int g = t * 512 + tid;                                          \
            int krow = g >> 4;                                              \
            int woct = g & 15;                                              \
            int kg = (cn) * 64 + krow;                                      \
            int ic = kg / 3;                                                \
            int kh = kg - 3 * ic;                                           \
            int hp = h + kh - 2;                                            \
            int sz = (hp >= 0) ? 16 : 0;                                    \
            int hpc = (hp >= 0) ? hp : 0;                                   \
            size_t eoff = (((size_t)(b * Cv + ic) * Hv + hpc) * Wv +        \
                           woct * 8) * 2;                                   \
            uint32_t dst = smb + XBUF_B + (db) * 16384 + krow * 256 +       \
                           ((woct ^ (krow & 7)) << 4);                      \
            CPA16Z(dst, gxh + eoff, sz);                                    \
        }                                                                   \
    } while (0)

    // ---- preamble: W (all 96KB) + X chunk 0
    {
#pragma unroll
        for (int j = 0; j < 12; j++)
            CPA16(smb + tid * 16 + j * 8192, gw + tid * 16 + j * 8192);
        STAGE_X(0, 0);
        CPA_COMMIT();
        CPA_WAIT0();
        __syncthreads();
    }

#pragma unroll
    for (int c = 0; c < 3; c++) {
        const int db = c & 1;
        if (c < 2) {
            STAGE_X(c + 1, db ^ 1);
            CPA_COMMIT();
        }

        const uint32_t a_h = smb + c * 32768 + (mw * 64 + l15) * 128;
        uint32_t bb[2];
#pragma unroll
        for (int np = 0; np < 2; np++) {
            int oct = ((nw * 32 + np * 16) >> 3) + wo;
            bb[np] = smb + XBUF_B + db * 16384 + krl * 256 + ((oct ^ l7) << 4);
        }
#pragma unroll
        for (int ks = 0; ks < 4; ks++) {
            uint32_t Bh[2][4];
#pragma unroll
            for (int np = 0; np < 2; np++)
                LDM4T(Bh[np], bb[np] + ks * 4096);
            const uint32_t swA = (uint32_t)(((2 * ks + lk) ^ l7) << 4);
#pragma unroll
            for (int mt = 0; mt < 4; mt++) {
                uint32_t A[4];
                LDM4(A, a_h + mt * 2048 + swA);
#pragma unroll
                for (int nt = 0; nt < 4; nt++) {
                    const int np = nt >> 1, ix = nt & 1;
                    mma_f16(acc[mt][nt], A, Bh[np][ix], Bh[np][2 + ix]);
                }
            }
        }

        if (c < 2) {
            CPA_WAIT0();
            __syncthreads();
        }
    }
    __syncthreads();  // stage buffers reusable (gates alias them)

    // ---- epilogue: bias + activation (MUFU.TANH) -> gates smem [w][260]
    const bool isg = (mw == 3);
#pragma unroll
    for (int mt = 0; mt < 4; mt++) {
        const int m0 = mw * 64 + mt * 16;
        const float blo = bias[m0 + r];
        const float bhi = bias[m0 + 8 + r];
#pragma unroll
        for (int nt = 0; nt < 4; nt++) {
            const int w0 = nw * 32 + nt * 8 + 2 * cl;
            float v0 = acc[mt][nt][0] + blo;
            float v1 = acc[mt][nt][1] + blo;
            float v2 = acc[mt][nt][2] + bhi;
            float v3 = acc[mt][nt][3] + bhi;
            if (isg) {
                v0 = tanh_f(v0); v1 = tanh_f(v1);
                v2 = tanh_f(v2); v3 = tanh_f(v3);
            } else {
                v0 = sigmoid_f(v0); v1 = sigmoid_f(v1);
                v2 = sigmoid_f(v2); v3 = sigmoid_f(v3);
            }
            smf[(size_t)w0 * GST + m0 + r]           = v0;
            smf[(size_t)(w0 + 1) * GST + m0 + r]     = v1;
            smf[(size_t)w0 * GST + m0 + 8 + r]       = v2;
            smf[(size_t)(w0 + 1) * GST + m0 + 8 + r] = v3;
        }
    }
    __syncthreads();

    // ---- LSTM scan: 8 segments of 16 w, parallel linear recurrence
    const int seg = tid >> 6;
    const int hc = tid & 63;
    {
        int gb = seg * 16 * GST + hc;
        float c = 0.0f, P = 1.0f;
#pragma unroll 8
        for (int j = 0; j < 16; j++) {
            float iv = smf[gb];
            float fv = smf[gb + 64];
            float gv = smf[gb + 192];
            c = fmaf(fv, c, iv * gv);
            P *= fv;
            smf[gb + 64] = c;
            smf[gb + 192] = P;
            gb += GST;
        }
        smf[PS_W + (seg * 64 + hc) * 2] = P;
        smf[PS_W + (seg * 64 + hc) * 2 + 1] = c;
    }
    __syncthreads();

    float cin = 0.0f;
#pragma unroll
    for (int s2 = 0; s2 < 7; s2++) {
        if (s2 < seg) {
            float P = smf[PS_W + (s2 * 64 + hc) * 2];
            float S = smf[PS_W + (s2 * 64 + hc) * 2 + 1];
            cin = fmaf(P, cin, S);
        }
    }

    {
        int gb = seg * 16 * GST + hc;
        float4* po = reinterpret_cast<float4*>(
            out + ((size_t)(b * HCv + hc) * Hv + h) * Wv + seg * 16);
        float hb[4];
#pragma unroll 4
        for (int j = 0; j < 16; j++) {
            float cp = smf[gb + 64];
            float fp = smf[gb + 192];
            float ov = smf[gb + 128];
            float cc = fmaf(fp, cin, cp);
            hb[j & 3] = ov * tanh_f(cc);
            if ((j & 3) == 3)
                po[j >> 2] = make_float4(hb[0], hb[1], hb[2], hb[3]);
            gb += GST;
        }
    }
}

extern "C" void kernel_launch(void* const* d_in, const int* in_sizes, int n_in,
                              void* d_out, int out_size) {
    const float* x    = (const float*)d_in[0];
    const float* wgt  = (const float*)d_in[1];
    const float* bias = (const float*)d_in[2];
    float* out = (float*)d_out;

    cudaFuncSetAttribute(rowlstm_fused,
                         cudaFuncAttributeMaxDynamicSharedMemorySize, SMEM_BYTES);

    prep_xw<<<8192, 256>>>(x, wgt);
    rowlstm_fused<<<Bv * Hv, 512, SMEM_BYTES>>>(bias, out);
}

// round 11
// speedup vs baseline: 1.4062x; 1.2035x over previous
#include <cuda_runtime.h>
#include <cuda_fp16.h>
#include <cstdint>

#define Bv 16
#define Cv 64
#define Hv 128
#define Wv 128
#define HCv 64
#define NROWS 2048
#define GRID 148

// Pre-baked W image (fp16): [chunk(3)][m(256)][k(64) octet-swizzled] = 96 KB
__device__ __align__(16) uint16_t g_wimg[3 * 256 * 64];
// Pre-rounded X plane (fp16), layout [b][ic][h][w]
#define XN ((size_t)Bv * Cv * Hv * Wv)
__device__ __align__(16) __half g_xhi[XN];

// ---- smem map (bytes) ----
// W resident: 3 x 32KB at 0 ; XBUF: 2 x 16KB at 98304
// GATES fp16 at 131072: [m(256)][138 halves] (stride 276B = 69 words == 5 mod 32)
// PS (scan partials, fp32 pairs) at 201728 (4KB)
#define XBUF_B 98304
#define GATE_B 131072
#define GROW_B 276
#define PS_B   201728
#define SMEM_BYTES 205824

extern __shared__ uint32_t smw[];

__device__ __forceinline__ uint32_t smem_u32(const void* p) {
    uint32_t a;
    asm("{ .reg .u64 t; cvta.to.shared.u64 t, %1; cvt.u32.u64 %0, t; }"
        : "=r"(a) : "l"(p));
    return a;
}

// single-instruction MUFU.TANH
__device__ __forceinline__ float tanh_f(float x) {
    float y;
    asm("tanh.approx.f32 %0, %1;" : "=f"(y) : "f"(x));
    return y;
}
// sigmoid via tanh: 1 MUFU + 1 FMA
__device__ __forceinline__ float sigmoid_f(float x) {
    return fmaf(tanh_f(0.5f * x), 0.5f, 0.5f);
}

__device__ __forceinline__ void mma_f16(float* c, const uint32_t* a,
                                        uint32_t b0, uint32_t b1) {
    asm volatile(
        "mma.sync.aligned.m16n8k16.row.col.f32.f16.f16.f32 "
        "{%0,%1,%2,%3}, {%4,%5,%6,%7}, {%8,%9}, {%0,%1,%2,%3};\n"
        : "+f"(c[0]), "+f"(c[1]), "+f"(c[2]), "+f"(c[3])
        : "r"(a[0]), "r"(a[1]), "r"(a[2]), "r"(a[3]), "r"(b0), "r"(b1));
}

#define LDM4(R, addr) \
    asm volatile("ldmatrix.sync.aligned.m8n8.x4.shared.b16 {%0,%1,%2,%3}, [%4];" \
        : "=r"((R)[0]), "=r"((R)[1]), "=r"((R)[2]), "=r"((R)[3]) : "r"(addr))
#define LDM4T(R, addr) \
    asm volatile("ldmatrix.sync.aligned.m8n8.x4.trans.shared.b16 {%0,%1,%2,%3}, [%4];" \
        : "=r"((R)[0]), "=r"((R)[1]), "=r"((R)[2]), "=r"((R)[3]) : "r"(addr))
#define CPA16(dst, src) \
    asm volatile("cp.async.ca.shared.global [%0], [%1], 16;" :: "r"(dst), "l"(src))
#define CPA16Z(dst, src, sz) \
    asm volatile("cp.async.ca.shared.global [%0], [%1], 16, %2;" \
                 :: "r"(dst), "l"(src), "r"(sz))
#define CPA_COMMIT() asm volatile("cp.async.commit_group;" ::: "memory")
#define CPA_WAIT0()  asm volatile("cp.async.wait_group 0;" ::: "memory")

__device__ __forceinline__ void sts32(uint32_t a, uint32_t v) {
    asm volatile("st.shared.u32 [%0], %1;" :: "r"(a), "r"(v) : "memory");
}
__device__ __forceinline__ uint32_t lds32(uint32_t a) {
    uint32_t v;
    asm volatile("ld.shared.u32 %0, [%1];" : "=r"(v) : "r"(a));
    return v;
}
__device__ __forceinline__ float2 h2f2(uint32_t w) {
    return __half22float2(*reinterpret_cast<__half2*>(&w));
}

// ---------------------------------------------------------------- prep kernel
__global__ void __launch_bounds__(256)
prep_xw(const float* __restrict__ x, const float* __restrict__ wgt) {
    if (blockIdx.x < 192) {
        int k = blockIdx.x;
        int m = threadIdx.x;
        float v = wgt[m * 192 + k];
        int c = k >> 6, kl = k & 63, o = kl >> 3, e = kl & 7;
        g_wimg[c * 16384 + m * 64 + (((o ^ (m & 7)) << 3) + e)] =
            __half_as_ushort(__float2half_rn(v));
    }
    size_t i = ((size_t)blockIdx.x * 256 + threadIdx.x) * 8;
    float4 a = *reinterpret_cast<const float4*>(x + i);
    float4 c = *reinterpret_cast<const float4*>(x + i + 4);
    float vf[8] = {a.x, a.y, a.z, a.w, c.x, c.y, c.z, c.w};
    uint32_t hw[4];
#pragma unroll
    for (int j = 0; j < 4; j++) {
        __half2 hh = __float22half2_rn(make_float2(vf[2 * j], vf[2 * j + 1]));
        hw[j] = *reinterpret_cast<uint32_t*>(&hh);
    }
    *reinterpret_cast<uint4*>(g_xhi + i) = make_uint4(hw[0], hw[1], hw[2], hw[3]);
}

// ---------------------------------------------------------------- persistent fused kernel
// 148 blocks, 512 threads = 16 warps (4m x 4n). Each block loops rows bh += 148.
// W (96KB) staged once; X streamed per chunk + cross-row prefetch; fp16 gates;
// register-resident scan partials.
__global__ void __launch_bounds__(512, 1)
rowlstm_fused(const float* __restrict__ bias, float* __restrict__ out) {
    const int tid = threadIdx.x;
    const int lane = tid & 31;
    const int wid = tid >> 5;
    const int mw = wid & 3;
    const int nw = wid >> 2;
    const int r = lane >> 2, cl = lane & 3;

    const uint32_t smb = smem_u32(smw);

    const int l7 = lane & 7, l15 = lane & 15, lk = lane >> 4;
    const int krl = l7 + ((lane & 16) >> 1);
    const int wo = (lane >> 3) & 1;

    uint64_t gw, gxh;
    asm("cvta.to.global.u64 %0, %1;" : "=l"(gw) : "l"((const void*)g_wimg));
    asm("cvta.to.global.u64 %0, %1;" : "=l"(gxh) : "l"((const void*)g_xhi));

    // bias hoisted (depends only on thread m-coords)
    float blo[4], bhi[4];
#pragma unroll
    for (int mt = 0; mt < 4; mt++) {
        blo[mt] = bias[mw * 64 + mt * 16 + r];
        bhi[mt] = bias[mw * 64 + mt * 16 + 8 + r];
    }
    const bool isg = (mw == 3);

    // scan thread mapping (row-invariant)
    const int seg = tid >> 6;      // 0..7, 16 w each
    const int hc = tid & 63;
    const uint32_t gsc = smb + GATE_B + (uint32_t)hc * GROW_B + (uint32_t)seg * 32;

#define STAGE_X(bb_, hh_, cn, db)                                           \
    do {                                                                    \
        _Pragma("unroll") for (int t = 0; t < 2; t++) {                     \
            int g = t * 512 + tid;                                          \
            int krow = g >> 4;                                              \
            int woct = g & 15;                                              \
            int kg = (cn) * 64 + krow;                                      \
            int ic = kg / 3;                                                \
            int kh = kg - 3 * ic;                                           \
            int hp = (hh_) + kh - 2;                                        \
            int sz = (hp >= 0) ? 16 : 0;                                    \
            int hpc = (hp >= 0) ? hp : 0;                                   \
            size_t eoff = (((size_t)((bb_) * Cv + ic) * Hv + hpc) * Wv +    \
                           woct * 8) * 2;                                   \
            uint32_t dst = smb + XBUF_B + (db) * 16384 + krow * 256 +       \
                           ((woct ^ (krow & 7)) << 4);                      \
            CPA16Z(dst, gxh + eoff, sz);                                    \
        }                                                                   \
    } while (0)

    // ---- preamble: W (96KB, once per SM) + first row chunk0
    {
#pragma unroll
        for (int j = 0; j < 12; j++)
            CPA16(smb + tid * 16 + j * 8192, gw + tid * 16 + j * 8192);
        STAGE_X(blockIdx.x >> 7, blockIdx.x & 127, 0, 0);
        CPA_COMMIT();
        CPA_WAIT0();
        __syncthreads();
    }

    int p = 0;
#pragma unroll 1
    for (int bh = blockIdx.x; bh < NROWS; bh += GRID) {
        const int b = bh >> 7, h = bh & 127;

        float acc[4][4][4];
#pragma unroll
        for (int mt = 0; mt < 4; mt++)
#pragma unroll
            for (int nt = 0; nt < 4; nt++)
#pragma unroll
                for (int q = 0; q < 4; q++) acc[mt][nt][q] = 0.0f;

#pragma unroll
        for (int c = 0; c < 3; c++) {
            const int db = (p + c) & 1;
            if (c < 2) {
                STAGE_X(b, h, c + 1, db ^ 1);
                CPA_COMMIT();
            }

            const uint32_t a_h = smb + c * 32768 + (mw * 64 + l15) * 128;
            uint32_t bb[2];
#pragma unroll
            for (int np = 0; np < 2; np++) {
                int oct = ((nw * 32 + np * 16) >> 3) + wo;
                bb[np] = smb + XBUF_B + db * 16384 + krl * 256 + ((oct ^ l7) << 4);
            }
#pragma unroll
            for (int ks = 0; ks < 4; ks++) {
                uint32_t Bh[2][4];
#pragma unroll
                for (int np = 0; np < 2; np++)
                    LDM4T(Bh[np], bb[np] + ks * 4096);
                const uint32_t swA = (uint32_t)(((2 * ks + lk) ^ l7) << 4);
#pragma unroll
                for (int mt = 0; mt < 4; mt++) {
                    uint32_t A[4];
                    LDM4(A, a_h + mt * 2048 + swA);
#pragma unroll
                    for (int nt = 0; nt < 4; nt++) {
                        const int np = nt >> 1, ix = nt & 1;
                        mma_f16(acc[mt][nt], A, Bh[np][ix], Bh[np][2 + ix]);
                    }
                }
            }

            if (c < 2) {
                CPA_WAIT0();
                __syncthreads();
            }
        }

        // prefetch next row chunk0 into buf p^1 (safe: chunk1 consumers synced)
        const int nbh = bh + GRID;
        if (nbh < NROWS) {
            STAGE_X(nbh >> 7, nbh & 127, 0, p ^ 1);
            CPA_COMMIT();
        }

        // ---- epilogue: bias + activation -> fp16 gates [m][138]
#pragma unroll
        for (int mt = 0; mt < 4; mt++) {
            const int m0 = mw * 64 + mt * 16;
            const uint32_t glo = smb + GATE_B + (uint32_t)(m0 + r) * GROW_B;
            const uint32_t ghi = glo + 8u * GROW_B;
#pragma unroll
            for (int nt = 0; nt < 4; nt++) {
                const uint32_t w2o = (uint32_t)(nw * 16 + nt * 4 + cl) * 4u;
                float v0 = acc[mt][nt][0] + blo[mt];
                float v1 = acc[mt][nt][1] + blo[mt];
                float v2 = acc[mt][nt][2] + bhi[mt];
                float v3 = acc[mt][nt][3] + bhi[mt];
                if (isg) {
                    v0 = tanh_f(v0); v1 = tanh_f(v1);
                    v2 = tanh_f(v2); v3 = tanh_f(v3);
                } else {
                    v0 = sigmoid_f(v0); v1 = sigmoid_f(v1);
                    v2 = sigmoid_f(v2); v3 = sigmoid_f(v3);
                }
                uint32_t p01, p23;
                asm("cvt.rn.f16x2.f32 %0, %1, %2;" : "=r"(p01) : "f"(v1), "f"(v0));
                asm("cvt.rn.f16x2.f32 %0, %1, %2;" : "=r"(p23) : "f"(v3), "f"(v2));
                sts32(glo + w2o, p01);
                sts32(ghi + w2o, p23);
            }
        }
        __syncthreads();

        // ---- LSTM scan: 8 segments x 16 w; partials in registers
        float cA[16], PA[16];
        {
            float cc = 0.f, pp = 1.f;
#pragma unroll
            for (int j = 0; j < 8; j++) {
                uint32_t iw = lds32(gsc + 4u * j);
                uint32_t fw = lds32(gsc + 4u * j + 64u * GROW_B);
                uint32_t gg = lds32(gsc + 4u * j + 192u * GROW_B);
                float2 iv = h2f2(iw), fv = h2f2(fw), gv = h2f2(gg);
                cc = fmaf(fv.x, cc, iv.x * gv.x); pp *= fv.x;
                cA[2 * j] = cc; PA[2 * j] = pp;
                cc = fmaf(fv.y, cc, iv.y * gv.y); pp *= fv.y;
                cA[2 * j + 1] = cc; PA[2 * j + 1] = pp;
            }
            uint32_t psa = smb + PS_B + (uint32_t)(seg * 64 + hc) * 8;
            asm volatile("st.shared.v2.f32 [%0], {%1, %2};"
                         :: "r"(psa), "f"(pp), "f"(cc) : "memory");
        }
        __syncthreads();

        float cin = 0.f;
#pragma unroll
        for (int s2 = 0; s2 < 7; s2++) {
            if (s2 < seg) {
                uint32_t psa = smb + PS_B + (uint32_t)(s2 * 64 + hc) * 8;
                float P, S;
                asm volatile("ld.shared.v2.f32 {%0, %1}, [%2];"
                             : "=f"(P), "=f"(S) : "r"(psa));
                cin = fmaf(P, cin, S);
            }
        }

        {
            float hv[16];
#pragma unroll
            for (int j = 0; j < 8; j++) {
                uint32_t ow = lds32(gsc + 4u * j + 128u * GROW_B);
                float2 ov = h2f2(ow);
                float t0 = fmaf(PA[2 * j], cin, cA[2 * j]);
                float t1 = fmaf(PA[2 * j + 1], cin, cA[2 * j + 1]);
                hv[2 * j] = ov.x * tanh_f(t0);
                hv[2 * j + 1] = ov.y * tanh_f(t1);
            }
            float* po = out + ((size_t)(b * HCv + hc) * Hv + h) * Wv + seg * 16;
            *reinterpret_cast<float4*>(po) =
                make_float4(hv[0], hv[1], hv[2], hv[3]);
            *reinterpret_cast<float4*>(po + 4) =
                make_float4(hv[4], hv[5], hv[6], hv[7]);
            *reinterpret_cast<float4*>(po + 8) =
                make_float4(hv[8], hv[9], hv[10], hv[11]);
            *reinterpret_cast<float4*>(po + 12) =
                make_float4(hv[12], hv[13], hv[14], hv[15]);
        }

        if (nbh < NROWS) CPA_WAIT0();
        __syncthreads();   // gates consumed; next-row X visible
        p ^= 1;
    }
}

extern "C" void kernel_launch(void* const* d_in, const int* in_sizes, int n_in,
                              void* d_out, int out_size) {
    const float* x    = (const float*)d_in[0];
    const float* wgt  = (const float*)d_in[1];
    const float* bias = (const float*)d_in[2];
    float* out = (float*)d_out;

    cudaFuncSetAttribute(rowlstm_fused,
                         cudaFuncAttributeMaxDynamicSharedMemorySize, SMEM_BYTES);

    prep_xw<<<8192, 256>>>(x, wgt);
    rowlstm_fused<<<GRID, 512, SMEM_BYTES>>>(bias, out);
}